// round 7
// baseline (speedup 1.0000x reference)
#include <cuda_runtime.h>
#include <cuda_fp16.h>
#include <stdint.h>

#define N_NODES 50000
#define D_FEAT  96
#define N_EDGES 800000

#define NBLOCKS 2048
#define NTHREADS 256
#define WARPS_PER_BLOCK (NTHREADS / 32)
#define CONV_BLOCKS 2048
#define ROW_BYTES (D_FEAT * 2)   // 192 bytes per fp16 row

// Scratch (device globals; no allocation allowed).
__device__ float        g_partials[NBLOCKS];
__device__ int          g_is_i64;
__device__ unsigned int g_done_counter;
__device__ __align__(16) __half g_feat_h[N_NODES * D_FEAT];  // 9.6 MB fp16 cache

// ---------------------------------------------------------------------------
// Kernel A: f32 -> f16 conversion + index-dtype detection + counter reset.
__global__ __launch_bounds__(NTHREADS)
void prep_kernel(const float* __restrict__ feat, const void* __restrict__ ei)
{
    if (blockIdx.x == 0 && threadIdx.x < 32) {
        // If buffer is really int32 (JAX x64-disabled), an int64 read fuses
        // two int32 indices -> value outside [0, N_NODES).
        const long long* p = (const long long*)ei;
        int t = threadIdx.x;
        long long v = __ldg(p + (long long)t * 24691);
        unsigned bad = __ballot_sync(0xffffffffu, (v < 0) || (v >= N_NODES));
        if (t == 0) {
            g_is_i64 = (bad == 0);
            g_done_counter = 0u;     // graph-replay safe reset
        }
    }

    const int n4 = (N_NODES * D_FEAT) / 4;
    uint2* __restrict__ dst = reinterpret_cast<uint2*>(g_feat_h);
    const float4* __restrict__ src = reinterpret_cast<const float4*>(feat);
    int i = blockIdx.x * blockDim.x + threadIdx.x;
    if (i < n4) {                      // n4 = 1.2M; grid covers it in 3 steps
        #pragma unroll 1
        for (; i < n4; i += gridDim.x * blockDim.x) {
            float4 v = __ldg(src + i);
            __half2 lo = __floats2half2_rn(v.x, v.y);
            __half2 hi = __floats2half2_rn(v.z, v.w);
            uint2 o;
            o.x = *reinterpret_cast<unsigned*>(&lo);
            o.y = *reinterpret_cast<unsigned*>(&hi);
            dst[i] = o;
        }
    }
}

__device__ __forceinline__ float sqrt_approx(float x)
{
    float r;
    asm("sqrt.approx.f32 %0, %1;" : "=f"(r) : "f"(x));
    return r;
}

// accumulate squared diff of one uint4 pair into a packed half2 accumulator
__device__ __forceinline__ void sqdiff_acc(uint4 a, uint4 b, __half2& q)
{
    __half2 a0 = *reinterpret_cast<__half2*>(&a.x);
    __half2 a1 = *reinterpret_cast<__half2*>(&a.y);
    __half2 a2 = *reinterpret_cast<__half2*>(&a.z);
    __half2 a3 = *reinterpret_cast<__half2*>(&a.w);
    __half2 b0 = *reinterpret_cast<__half2*>(&b.x);
    __half2 b1 = *reinterpret_cast<__half2*>(&b.y);
    __half2 b2 = *reinterpret_cast<__half2*>(&b.z);
    __half2 b3 = *reinterpret_cast<__half2*>(&b.w);
    __half2 d0 = __hsub2(a0, b0);
    __half2 d1 = __hsub2(a1, b1);
    __half2 d2 = __hsub2(a2, b2);
    __half2 d3 = __hsub2(a3, b3);
    q = __hfma2(d0, d0, q);
    q = __hfma2(d1, d1, q);
    q = __hfma2(d2, d2, q);
    q = __hfma2(d3, d3, q);
}

// fetch the (src,dst) index pair for edge e
__device__ __forceinline__ void load_idx(const long long* ei64, const int* ei32,
                                         int is64, int e, int& s, int& d)
{
    if (is64) {
        s = (int)__ldg(ei64 + e);
        d = (int)__ldg(ei64 + N_EDGES + e);
    } else {
        s = __ldg(ei32 + e);
        d = __ldg(ei32 + N_EDGES + e);
    }
}

// ---------------------------------------------------------------------------
// Kernel B: QUAD-per-edge gather + norm + fused final reduction.
// launch_bounds minBlocks=7 caps regs at 36 -> ~87.5% occupancy.
__global__ __launch_bounds__(NTHREADS, 7)
void graph_smooth_edge_kernel(const void* __restrict__ edge_index,
                              float* __restrict__ out)
{
    const int lane   = threadIdx.x & 31;
    const int q      = lane & 3;        // lane within quad
    const int quad   = lane >> 2;       // 0..7 -> which edge of the 8
    const int warpIn = threadIdx.x >> 5;
    const int gwarp  = (blockIdx.x * NTHREADS + threadIdx.x) >> 5;
    const int nwarps = (gridDim.x * NTHREADS) >> 5;

    const int is64 = g_is_i64;
    const long long* ei64 = (const long long*)edge_index;
    const int*       ei32 = (const int*)edge_index;
    const char* base = (const char*)g_feat_h;

    float acc = 0.0f;   // meaningful in quad-leader lanes (q == 0)

    const int estep = nwarps * 8;
    int e0 = gwarp * 8;

    // prefetch indices for the first iteration
    int s = 0, d = 0;
    if (e0 < N_EDGES)
        load_idx(ei64, ei32, is64, e0 + quad, s, d);

    // N_EDGES % 8 == 0; warp strides cover groups of 8 edges.
    for (; e0 < N_EDGES; e0 += estep) {
        const uint4* ps = reinterpret_cast<const uint4*>(base + (unsigned)s * ROW_BYTES);
        const uint4* pd = reinterpret_cast<const uint4*>(base + (unsigned)d * ROW_BYTES);

        // 6 independent gathers -> good MLP
        uint4 a0 = __ldg(ps + q);
        uint4 b0 = __ldg(pd + q);
        uint4 a1 = __ldg(ps + q + 4);
        uint4 b1 = __ldg(pd + q + 4);
        uint4 a2 = __ldg(ps + q + 8);
        uint4 b2 = __ldg(pd + q + 8);

        // prefetch next iteration's indices while gathers are in flight
        const int en = e0 + estep;
        if (en < N_EDGES)
            load_idx(ei64, ei32, is64, en + quad, s, d);

        __half2 qacc = __float2half2_rn(0.0f);
        sqdiff_acc(a0, b0, qacc);
        sqdiff_acc(a1, b1, qacc);
        sqdiff_acc(a2, b2, qacc);

        float2 f = __half22float2(qacc);
        float part = f.x + f.y;

        // reduce within quad (width 4)
        part += __shfl_down_sync(0xffffffffu, part, 2, 4);
        part += __shfl_down_sync(0xffffffffu, part, 1, 4);

        if (q == 0)
            acc += sqrt_approx(part);
    }

    // warp reduce (only q==0 lanes hold nonzero acc)
    #pragma unroll
    for (int off = 16; off > 0; off >>= 1)
        acc += __shfl_down_sync(0xffffffffu, acc, off);

    __shared__ float smem[WARPS_PER_BLOCK];
    __shared__ bool  amLast;
    if (lane == 0) smem[warpIn] = acc;
    __syncthreads();

    if (warpIn == 0) {
        float v = (lane < WARPS_PER_BLOCK) ? smem[lane] : 0.0f;
        #pragma unroll
        for (int off = 16; off > 0; off >>= 1)
            v += __shfl_down_sync(0xffffffffu, v, off);
        if (lane == 0) {
            g_partials[blockIdx.x] = v;
            __threadfence();
            unsigned prev = atomicAdd(&g_done_counter, 1u);
            amLast = (prev == NBLOCKS - 1);
        }
    }
    __syncthreads();

    // Last block performs the deterministic final reduction (fixed order).
    if (amLast) {
        const int tid = threadIdx.x;
        float v = 0.0f;
        #pragma unroll
        for (int i = 0; i < NBLOCKS / NTHREADS; i++)
            v += __ldcg(&g_partials[tid + i * NTHREADS]);

        #pragma unroll
        for (int off = 16; off > 0; off >>= 1)
            v += __shfl_down_sync(0xffffffffu, v, off);

        if (lane == 0) smem[warpIn] = v;
        __syncthreads();

        if (warpIn == 0) {
            float sres = (lane < WARPS_PER_BLOCK) ? smem[lane] : 0.0f;
            #pragma unroll
            for (int off = 16; off > 0; off >>= 1)
                sres += __shfl_down_sync(0xffffffffu, sres, off);
            if (lane == 0)
                out[0] = sres * (1.0f / (float)N_EDGES);  // WEIGHT = 1.0
        }
    }
}

extern "C" void kernel_launch(void* const* d_in, const int* in_sizes, int n_in,
                              void* d_out, int out_size)
{
    const float* feat = (const float*)d_in[0];  // (50000, 96) f32
    const void*  ei   = d_in[1];                // (2, 800000) int64-or-int32
    float*       out  = (float*)d_out;          // scalar f32

    prep_kernel<<<CONV_BLOCKS, NTHREADS>>>(feat, ei);
    graph_smooth_edge_kernel<<<NBLOCKS, NTHREADS>>>(ei, out);
}

// round 8
// speedup vs baseline: 1.1223x; 1.1223x over previous
#include <cuda_runtime.h>
#include <cuda_fp16.h>
#include <stdint.h>

#define N_NODES 50000
#define D_FEAT  96
#define N_EDGES 800000

#define NBLOCKS 2048
#define NTHREADS 256
#define WARPS_PER_BLOCK (NTHREADS / 32)
#define CONV_BLOCKS 2048
#define ROW_BYTES (D_FEAT * 2)   // 192 bytes per fp16 row

// Scratch (device globals; no allocation allowed).
__device__ float        g_partials[NBLOCKS];
__device__ int          g_is_i64;
__device__ unsigned int g_done_counter;
__device__ __align__(16) __half g_feat_h[N_NODES * D_FEAT];  // 9.6 MB fp16 cache

// ---------------------------------------------------------------------------
// Kernel A: f32 -> f16 conversion + index-dtype detection + counter reset.
__global__ __launch_bounds__(NTHREADS)
void prep_kernel(const float* __restrict__ feat, const void* __restrict__ ei)
{
    if (blockIdx.x == 0 && threadIdx.x < 32) {
        // If buffer is really int32 (JAX x64-disabled), an int64 read fuses
        // two int32 indices -> value outside [0, N_NODES).
        const long long* p = (const long long*)ei;
        int t = threadIdx.x;
        long long v = __ldg(p + (long long)t * 24691);
        unsigned bad = __ballot_sync(0xffffffffu, (v < 0) || (v >= N_NODES));
        if (t == 0) {
            g_is_i64 = (bad == 0);
            g_done_counter = 0u;     // graph-replay safe reset
        }
    }

    const int n4 = (N_NODES * D_FEAT) / 4;
    uint2* __restrict__ dst = reinterpret_cast<uint2*>(g_feat_h);
    const float4* __restrict__ src = reinterpret_cast<const float4*>(feat);
    for (int i = blockIdx.x * blockDim.x + threadIdx.x; i < n4;
         i += gridDim.x * blockDim.x) {
        float4 v = __ldg(src + i);
        __half2 lo = __floats2half2_rn(v.x, v.y);
        __half2 hi = __floats2half2_rn(v.z, v.w);
        uint2 o;
        o.x = *reinterpret_cast<unsigned*>(&lo);
        o.y = *reinterpret_cast<unsigned*>(&hi);
        dst[i] = o;
    }
}

__device__ __forceinline__ float sqrt_approx(float x)
{
    float r;
    asm("sqrt.approx.f32 %0, %1;" : "=f"(r) : "f"(x));
    return r;
}

// accumulate squared diff of one uint4 pair into a packed half2 accumulator
__device__ __forceinline__ void sqdiff_acc(uint4 a, uint4 b, __half2& q)
{
    __half2 a0 = *reinterpret_cast<__half2*>(&a.x);
    __half2 a1 = *reinterpret_cast<__half2*>(&a.y);
    __half2 a2 = *reinterpret_cast<__half2*>(&a.z);
    __half2 a3 = *reinterpret_cast<__half2*>(&a.w);
    __half2 b0 = *reinterpret_cast<__half2*>(&b.x);
    __half2 b1 = *reinterpret_cast<__half2*>(&b.y);
    __half2 b2 = *reinterpret_cast<__half2*>(&b.z);
    __half2 b3 = *reinterpret_cast<__half2*>(&b.w);
    __half2 d0 = __hsub2(a0, b0);
    __half2 d1 = __hsub2(a1, b1);
    __half2 d2 = __hsub2(a2, b2);
    __half2 d3 = __hsub2(a3, b3);
    q = __hfma2(d0, d0, q);
    q = __hfma2(d1, d1, q);
    q = __hfma2(d2, d2, q);
    q = __hfma2(d3, d3, q);
}

// guarded index fetch: edges >= N_EDGES map to node 0 (zero contribution,
// since row0 - row0 == 0 -> sqrt(0) == 0). Branch-free tail handling.
__device__ __forceinline__ void load_idx_g(const long long* ei64, const int* ei32,
                                           int is64, int e, int& s, int& d)
{
    if (e < N_EDGES) {
        if (is64) {
            s = (int)__ldg(ei64 + e);
            d = (int)__ldg(ei64 + N_EDGES + e);
        } else {
            s = __ldg(ei32 + e);
            d = __ldg(ei32 + N_EDGES + e);
        }
    } else {
        s = 0; d = 0;
    }
}

// ---------------------------------------------------------------------------
// Kernel B: QUAD-per-edge gather, 2 edge-groups per warp-iteration (MLP=12),
// next-iteration index prefetch, fused deterministic final reduction.
// NO register cap: per-warp MLP beats occupancy here (R7 lesson).
__global__ __launch_bounds__(NTHREADS)
void graph_smooth_edge_kernel(const void* __restrict__ edge_index,
                              float* __restrict__ out)
{
    const int lane   = threadIdx.x & 31;
    const int q      = lane & 3;        // lane within quad
    const int quad   = lane >> 2;       // 0..7 -> which edge of the 8
    const int warpIn = threadIdx.x >> 5;
    const int gwarp  = (blockIdx.x * NTHREADS + threadIdx.x) >> 5;
    const int nwarps = (gridDim.x * NTHREADS) >> 5;

    const int is64 = g_is_i64;
    const long long* ei64 = (const long long*)edge_index;
    const int*       ei32 = (const int*)edge_index;
    const char* base = (const char*)g_feat_h;

    float acc = 0.0f;   // meaningful in quad-leader lanes (q == 0)

    const int estep   = nwarps * 8;     // edges per group-step
    const int stride2 = estep * 2;

    int e0 = gwarp * 8;
    int s0, d0, s1, d1;
    load_idx_g(ei64, ei32, is64, e0 + quad,         s0, d0);
    load_idx_g(ei64, ei32, is64, e0 + estep + quad, s1, d1);

    for (; e0 < N_EDGES; e0 += stride2) {
        const uint4* ps0 = reinterpret_cast<const uint4*>(base + (unsigned)s0 * ROW_BYTES);
        const uint4* pd0 = reinterpret_cast<const uint4*>(base + (unsigned)d0 * ROW_BYTES);
        const uint4* ps1 = reinterpret_cast<const uint4*>(base + (unsigned)s1 * ROW_BYTES);
        const uint4* pd1 = reinterpret_cast<const uint4*>(base + (unsigned)d1 * ROW_BYTES);

        // 12 independent gathers in flight
        uint4 a0 = __ldg(ps0 + q);
        uint4 b0 = __ldg(pd0 + q);
        uint4 a1 = __ldg(ps0 + q + 4);
        uint4 b1 = __ldg(pd0 + q + 4);
        uint4 a2 = __ldg(ps0 + q + 8);
        uint4 b2 = __ldg(pd0 + q + 8);
        uint4 c0 = __ldg(ps1 + q);
        uint4 e0v= __ldg(pd1 + q);
        uint4 c1 = __ldg(ps1 + q + 4);
        uint4 e1v= __ldg(pd1 + q + 4);
        uint4 c2 = __ldg(ps1 + q + 8);
        uint4 e2v= __ldg(pd1 + q + 8);

        // prefetch next iteration's indices while gathers are in flight
        const int en = e0 + stride2;
        load_idx_g(ei64, ei32, is64, en + quad,         s0, d0);
        load_idx_g(ei64, ei32, is64, en + estep + quad, s1, d1);

        __half2 qa = __float2half2_rn(0.0f);
        sqdiff_acc(a0, b0, qa);
        sqdiff_acc(a1, b1, qa);
        sqdiff_acc(a2, b2, qa);
        __half2 qb = __float2half2_rn(0.0f);
        sqdiff_acc(c0, e0v, qb);
        sqdiff_acc(c1, e1v, qb);
        sqdiff_acc(c2, e2v, qb);

        float2 fa = __half22float2(qa);
        float2 fb = __half22float2(qb);
        float p0 = fa.x + fa.y;
        float p1 = fb.x + fb.y;

        // reduce within quad (width 4), both groups
        p0 += __shfl_down_sync(0xffffffffu, p0, 2, 4);
        p0 += __shfl_down_sync(0xffffffffu, p0, 1, 4);
        p1 += __shfl_down_sync(0xffffffffu, p1, 2, 4);
        p1 += __shfl_down_sync(0xffffffffu, p1, 1, 4);

        if (q == 0)
            acc += sqrt_approx(p0) + sqrt_approx(p1);
    }

    // warp reduce (only q==0 lanes hold nonzero acc)
    #pragma unroll
    for (int off = 16; off > 0; off >>= 1)
        acc += __shfl_down_sync(0xffffffffu, acc, off);

    __shared__ float smem[WARPS_PER_BLOCK];
    __shared__ bool  amLast;
    if (lane == 0) smem[warpIn] = acc;
    __syncthreads();

    if (warpIn == 0) {
        float v = (lane < WARPS_PER_BLOCK) ? smem[lane] : 0.0f;
        #pragma unroll
        for (int off = 16; off > 0; off >>= 1)
            v += __shfl_down_sync(0xffffffffu, v, off);
        if (lane == 0) {
            g_partials[blockIdx.x] = v;
            __threadfence();
            unsigned prev = atomicAdd(&g_done_counter, 1u);
            amLast = (prev == NBLOCKS - 1);
        }
    }
    __syncthreads();

    // Last block performs the deterministic final reduction (fixed order).
    if (amLast) {
        const int tid = threadIdx.x;
        float v = 0.0f;
        #pragma unroll
        for (int i = 0; i < NBLOCKS / NTHREADS; i++)
            v += __ldcg(&g_partials[tid + i * NTHREADS]);

        #pragma unroll
        for (int off = 16; off > 0; off >>= 1)
            v += __shfl_down_sync(0xffffffffu, v, off);

        if (lane == 0) smem[warpIn] = v;
        __syncthreads();

        if (warpIn == 0) {
            float sres = (lane < WARPS_PER_BLOCK) ? smem[lane] : 0.0f;
            #pragma unroll
            for (int off = 16; off > 0; off >>= 1)
                sres += __shfl_down_sync(0xffffffffu, sres, off);
            if (lane == 0)
                out[0] = sres * (1.0f / (float)N_EDGES);  // WEIGHT = 1.0
        }
    }
}

extern "C" void kernel_launch(void* const* d_in, const int* in_sizes, int n_in,
                              void* d_out, int out_size)
{
    const float* feat = (const float*)d_in[0];  // (50000, 96) f32
    const void*  ei   = d_in[1];                // (2, 800000) int64-or-int32
    float*       out  = (float*)d_out;          // scalar f32

    prep_kernel<<<CONV_BLOCKS, NTHREADS>>>(feat, ei);
    graph_smooth_edge_kernel<<<NBLOCKS, NTHREADS>>>(ei, out);
}